// round 11
// baseline (speedup 1.0000x reference)
#include <cuda_runtime.h>
#include <math.h>

// Problem dims (fixed by the reference)
#define NB 2048   // batch
#define NI 256    // inner / contraction dim j
#define NO 256    // output dim i

#define J_CH 32                    // j per smem stage
#define NCHUNK (NI / J_CH)         // 8
#define ROWS_CH (J_CH / 2)         // 16 j-pair rows per chunk
// per-buffer float offsets: cx[512] sx[512] nc[1024] so[1024]
#define OFF_SX 512
#define OFF_NC 1024
#define OFF_SO 2048
#define BUF_FLOATS 3072            // 12 KB per buffer
#define BUF_BYTES  12288

typedef unsigned long long ull;

// Global trig tables, pair-interleaved j-major:
//   g_cx2[(j2*R + r)*2 + (j&1)],  R = NB (x-side) or NO (o-side)
__device__ __align__(16) float g_cx2[NI * NB];  // cos(phi0 + x)
__device__ __align__(16) float g_sx2[NI * NB];  // sin(phi0 + x)
__device__ __align__(16) float g_nc2[NI * NO];  // -2*rho*cos(off)
__device__ __align__(16) float g_so2[NI * NO];  //  2*rho*sin(off)

// ---------------- prep: both tables in one launch ----------------
__global__ void prep_all(const float* __restrict__ x, const float* __restrict__ off,
                         float phi0, float two_rho) {
    __shared__ float tile[32][33];
    const int blk = blockIdx.x;
    const float* src;
    float *dc, *ds;
    int R, r0, j0;
    float addp, mc, ms;
    if (blk < 512) {               // x-table: 64 b-tiles x 8 j-tiles
        r0 = (blk >> 3) * 32; j0 = (blk & 7) * 32;
        src = x;  dc = g_cx2; ds = g_sx2; R = NB;
        addp = phi0; mc = 1.0f; ms = 1.0f;
    } else {                       // off-table: 8 i-tiles x 8 j-tiles
        int q = blk - 512;
        r0 = (q >> 3) * 32; j0 = (q & 7) * 32;
        src = off; dc = g_nc2; ds = g_so2; R = NO;
        addp = 0.0f; mc = -two_rho; ms = two_rho;
    }
    const int lane = threadIdx.x & 31;
    const int w8   = threadIdx.x >> 5;
    #pragma unroll
    for (int rr = 0; rr < 4; ++rr)
        tile[w8 + rr * 8][lane] = src[(r0 + w8 + rr * 8) * NI + j0 + lane];
    __syncthreads();
    #pragma unroll
    for (int k = 0; k < 4; ++k) {
        int jj = w8 + k * 8, ri = lane;
        float s, c;
        __sincosf(addp + tile[ri][jj], &s, &c);
        int idx = (((j0 + jj) >> 1) * R + (r0 + ri)) * 2 + (jj & 1);
        dc[idx] = mc * c;
        ds[idx] = ms * s;
    }
}

// ---------------- packed f32x2 + misc helpers ----------------
__device__ __forceinline__ ull ffma2(ull a, ull b, ull c) {
    ull d;
    asm("fma.rn.f32x2 %0, %1, %2, %3;" : "=l"(d) : "l"(a), "l"(b), "l"(c));
    return d;
}
__device__ __forceinline__ ull fadd2(ull a, ull b) {
    ull d;
    asm("add.rn.f32x2 %0, %1, %2;" : "=l"(d) : "l"(a), "l"(b));
    return d;
}
__device__ __forceinline__ ull fmul2(ull a, ull b) {
    ull d;
    asm("mul.rn.f32x2 %0, %1, %2;" : "=l"(d) : "l"(a), "l"(b));
    return d;
}
__device__ __forceinline__ float2 u2f(ull v) {
    float2 r;
    asm("mov.b64 {%0, %1}, %2;" : "=f"(r.x), "=f"(r.y) : "l"(v));
    return r;
}
__device__ __forceinline__ float frcp(float x) {
    float r;
    asm("rcp.approx.f32 %0, %1;" : "=f"(r) : "f"(x));
    return r;
}
__device__ __forceinline__ void cp16(unsigned dst, const void* src) {
    asm volatile("cp.async.ca.shared.global [%0], [%1], 16;\n" :: "r"(dst), "l"(src));
}

// 4 j-terms fused: sum 1/d = (S.x*P.y + S.y*P.x) * rcp(P.x*P.y), S=D+E, P=D*E.
#define QCELL(acc, cA, sA, cB, sB, nA, oA, nB, oB)                     \
    do {                                                               \
        ull D_ = ffma2((cA), (nA), ffma2((sA), (oA), Q2));             \
        ull E_ = ffma2((cB), (nB), ffma2((sB), (oB), Q2));             \
        float2 S_ = u2f(fadd2(D_, E_));                                \
        float2 P_ = u2f(fmul2(D_, E_));                                \
        (acc) = fmaf(fmaf(S_.x, P_.y, S_.y * P_.x),                    \
                     frcp(P_.x * P_.y), (acc));                        \
    } while (0)

// CTA: 128 threads, tile 16(b) x 32(i), micro-tile 2b x 2i.
// grid (128, 8) = 1024 CTAs -> ~7 CTAs/SM, wave imbalance ~1.01.
// Warp-level: 8 distinct b-groups -> cx LDS.128 = 1 wavefront (128B).
__global__ __launch_bounds__(128, 7) void photonic_main(float* __restrict__ out,
                                                        ull Q2, float negK) {
    extern __shared__ __align__(16) float sbuf[];   // 2 * 12 KB

    const int t  = threadIdx.x;
    const int tx = t & 7;                    // 8 groups along b (2 b each)
    const int ty = t >> 3;                   // 16 groups along i (2 i each)
    const int b_blk = blockIdx.x * 16;
    const int i_blk = blockIdx.y * 32;

    const unsigned sb = (unsigned)__cvta_generic_to_shared(sbuf);

    // fill coords: cx/sx have 128 16B-chunks each (thread t -> chunk t);
    // nc/so have 256 chunks (threads t and t+128).
    const int xjp = t >> 3, xseg = t & 7;
    const int ojp = t >> 4, oseg = t & 15;

    const float* pxc = g_cx2 + (xjp * NB + b_blk) * 2 + xseg * 4;
    const float* pxs = g_sx2 + (xjp * NB + b_blk) * 2 + xseg * 4;
    const float* poc0 = g_nc2 + ((ojp    ) * NO + i_blk) * 2 + oseg * 4;
    const float* poc1 = g_nc2 + ((ojp + 8) * NO + i_blk) * 2 + oseg * 4;
    const float* pos0 = g_so2 + ((ojp    ) * NO + i_blk) * 2 + oseg * 4;
    const float* pos1 = g_so2 + ((ojp + 8) * NO + i_blk) * 2 + oseg * 4;
    const int xstep = ROWS_CH * NB * 2;      // 65536 floats per chunk
    const int ostep = ROWS_CH * NO * 2;      // 8192 floats per chunk

    auto issue = [&](int c, int p) {
        unsigned base = sb + (unsigned)(p * BUF_BYTES);
        cp16(base + (unsigned)(t * 16),                          pxc  + c * xstep);
        cp16(base + (unsigned)(OFF_SX * 4 + t * 16),             pxs  + c * xstep);
        cp16(base + (unsigned)(OFF_NC * 4 + t * 16),             poc0 + c * ostep);
        cp16(base + (unsigned)(OFF_NC * 4 + (t + 128) * 16),     poc1 + c * ostep);
        cp16(base + (unsigned)(OFF_SO * 4 + t * 16),             pos0 + c * ostep);
        cp16(base + (unsigned)(OFF_SO * 4 + (t + 128) * 16),     pos1 + c * ostep);
        asm volatile("cp.async.commit_group;\n" ::);
    };

    float a00 = 0.f, a01 = 0.f, a10 = 0.f, a11 = 0.f;

    issue(0, 0);
    issue(1, 1);

    #pragma unroll 1
    for (int c = 0; c < NCHUNK; ++c) {
        if (c < NCHUNK - 1) asm volatile("cp.async.wait_group 1;\n" ::);
        else                asm volatile("cp.async.wait_group 0;\n" ::);
        __syncthreads();

        const int p = c & 1;
        const float* buf = sbuf + p * BUF_FLOATS;
        const float* cxb = buf +          tx * 4;   // 2 b's, pair-interleaved (row stride 32)
        const float* sxb = buf + OFF_SX + tx * 4;
        const float* ncb = buf + OFF_NC + ty * 4;   // 2 i's (row stride 64)
        const float* sob = buf + OFF_SO + ty * 4;

        #pragma unroll
        for (int jp = 0; jp < ROWS_CH; jp += 2) {   // 4 j per iter, imm offsets
            const ulonglong2 cxA = *(const ulonglong2*)(cxb + (jp    ) * 32);
            const ulonglong2 cxB = *(const ulonglong2*)(cxb + (jp + 1) * 32);
            const ulonglong2 sxA = *(const ulonglong2*)(sxb + (jp    ) * 32);
            const ulonglong2 sxB = *(const ulonglong2*)(sxb + (jp + 1) * 32);
            const ulonglong2 nA  = *(const ulonglong2*)(ncb + (jp    ) * 64);
            const ulonglong2 nB  = *(const ulonglong2*)(ncb + (jp + 1) * 64);
            const ulonglong2 oA  = *(const ulonglong2*)(sob + (jp    ) * 64);
            const ulonglong2 oB  = *(const ulonglong2*)(sob + (jp + 1) * 64);

            // (b0, i0) / (b0, i1)
            QCELL(a00, cxA.x, sxA.x, cxB.x, sxB.x, nA.x, oA.x, nB.x, oB.x);
            QCELL(a01, cxA.x, sxA.x, cxB.x, sxB.x, nA.y, oA.y, nB.y, oB.y);
            // (b1, i0) / (b1, i1)
            QCELL(a10, cxA.y, sxA.y, cxB.y, sxB.y, nA.x, oA.x, nB.x, oB.x);
            QCELL(a11, cxA.y, sxA.y, cxB.y, sxB.y, nA.y, oA.y, nB.y, oB.y);
        }
        __syncthreads();   // all reads of buffer p done
        if (c + 2 < NCHUNK) issue(c + 2, p);
    }

    const int b0 = b_blk + tx * 2;
    const int i0 = i_blk + ty * 2;
    float2 r0, r1;
    r0.x = fmaf(negK, a00, (float)NI);
    r0.y = fmaf(negK, a01, (float)NI);
    r1.x = fmaf(negK, a10, (float)NI);
    r1.y = fmaf(negK, a11, (float)NI);
    *(float2*)(out + (b0 + 0) * NO + i0) = r0;
    *(float2*)(out + (b0 + 1) * NO + i0) = r1;
}

extern "C" void kernel_launch(void* const* d_in, const int* in_sizes, int n_in,
                              void* d_out, int out_size) {
    const float* x   = (const float*)d_in[0];   // input_matrix [2048, 256]
    const float* off = (const float*)d_in[1];   // phase_offset [256, 256]
    float* out = (float*)d_out;                 // [2048, 256]

    // Physics constants
    const double PI     = 3.14159265358979323846;
    const double RADIUS = 5e-6;
    const double KAPPA  = 0.1;
    const double N_EFF  = 3.48;
    const double LAMBDA = 1.55e-6;
    const double LOSS_A = 0.99;

    const double t   = sqrt(1.0 - KAPPA);
    const double a   = LOSS_A;
    const double rho = a * t;
    const double phi0 = fmod(2.0 * PI * N_EFF * (2.0 * PI * RADIUS) / LAMBDA, 2.0 * PI);

    const float Qc      = (float)(1.0 + rho * rho);
    const float two_rho = (float)(2.0 * rho);
    const float negK    = (float)(-(1.0 - t * t) * (1.0 - a * a));

    unsigned int qbits;
    memcpy(&qbits, &Qc, 4);
    const ull Q2 = ((ull)qbits << 32) | qbits;   // packed (Qc, Qc)

    prep_all<<<576, 256>>>(x, off, (float)phi0, two_rho);

    const int smem_bytes = 2 * BUF_BYTES;   // 24 KB
    cudaFuncSetAttribute(photonic_main,
                         cudaFuncAttributeMaxDynamicSharedMemorySize, smem_bytes);
    dim3 grid(NB / 16, NO / 32);   // (128, 8) = 1024 CTAs
    photonic_main<<<grid, 128, smem_bytes>>>(out, Q2, negK);
}